// round 6
// baseline (speedup 1.0000x reference)
#include <cuda_runtime.h>
#include <cstdint>
#include <cstddef>

// Problem constants
constexpr int cB = 4;
constexpr int cL = 1024;
constexpr int cD = 768;
constexpr int cN = 16;
constexpr int cR = 48;
constexpr int cM = cB * cL;          // 4096 rows
constexpr int XPW = cR + 4 * cN;     // 112 (true x_proj width)
constexpr int XPN = 128;             // padded x_proj width

// ---------------------------------------------------------------------------
// Scratch (static device globals — no allocation)
// ---------------------------------------------------------------------------
__device__ float g_xin[cM * cD];     // silu(xz[:, :D])
__device__ float g_zg [cM * cD];     // silu(xz[:, D:])
__device__ float g_xpw[cD * XPN];    // padded x_proj_w
__device__ float g_xp [cM * XPN];    // x_in @ x_proj_w (padded cols 112..127 = 0)
__device__ float g_dt [cM * cD];     // softplus(dt_pre)
__device__ float g_xdt[cM * cD];     // x_in * dt
__device__ float g_yg [cM * cD];     // ys * silu(z)

// ---------------------------------------------------------------------------
// Helpers
// ---------------------------------------------------------------------------
__device__ __forceinline__ float siluf(float x) {
    return x / (1.0f + __expf(-x));
}
__device__ __forceinline__ float softplusf(float x) {
    return fmaxf(x, 0.0f) + log1pf(__expf(-fabsf(x)));
}

// Packed dual-fp32 FMA (Blackwell): d = a*b + d elementwise on f32x2
__device__ __forceinline__ void ffma2(unsigned long long& d,
                                      unsigned long long a,
                                      unsigned long long b) {
    asm("fma.rn.f32x2 %0, %1, %2, %0;" : "+l"(d) : "l"(a), "l"(b));
}
__device__ __forceinline__ unsigned long long pack2(float v) {
    unsigned long long r;
    asm("mov.b64 %0, {%1, %2};" : "=l"(r) : "f"(v), "f"(v));
    return r;
}
__device__ __forceinline__ void unpack2(unsigned long long p, float& lo, float& hi) {
    asm("mov.b64 {%0, %1}, %2;" : "=f"(lo), "=f"(hi) : "l"(p));
}

// ---------------------------------------------------------------------------
// Epilogues
//  0: split-silu  (in_proj)   : col<D -> C0=silu ; else C1=silu
//  1: plain store (x_proj)
//  2: softplus+xdt (dt_proj)  : C0=softplus(v+bias) ; C1=C0*aux
//  3: bias        (out_proj)
// ---------------------------------------------------------------------------
template<int EPI>
__device__ __forceinline__ void epi_store(int m, int col, float v,
                                          float* C0, float* C1,
                                          const float* bias, const float* aux,
                                          int ldc) {
    if constexpr (EPI == 0) {
        float s = siluf(v);
        if (col < cD) C0[(size_t)m * cD + col] = s;
        else          C1[(size_t)m * cD + (col - cD)] = s;
    } else if constexpr (EPI == 1) {
        C0[(size_t)m * ldc + col] = v;
    } else if constexpr (EPI == 2) {
        float dtv = softplusf(v + bias[col]);
        size_t idx = (size_t)m * cD + col;
        C0[idx] = dtv;
        C1[idx] = dtv * aux[idx];
    } else {
        C0[(size_t)m * ldc + col] = v + bias[col];
    }
}

// ---------------------------------------------------------------------------
// Tiled SGEMM with f32x2 packed FMA. C = A(MxK,lda) @ B(KxN,ldb), row-major.
// All dims are exact multiples of the tile sizes (by construction).
// ---------------------------------------------------------------------------
template<int BM, int BN, int BK, int TM, int TN, int EPI>
__global__ __launch_bounds__((BM / TM) * (BN / TN))
void gemm_kernel(const float* __restrict__ A, const float* __restrict__ Bw,
                 float* __restrict__ C0, float* __restrict__ C1,
                 const float* __restrict__ bias, const float* __restrict__ aux,
                 int K, int lda, int ldb, int ldc) {
    constexpr int TX = BN / TN;
    constexpr int TY = BM / TM;
    constexpr int THREADS = TX * TY;
    constexpr int AF4 = BM * BK / (4 * THREADS);
    constexpr int BF4 = BK * BN / (4 * THREADS);

    __shared__ __align__(16) float As[BK][BM + 4];  // +4 pad: spread STS banks
    __shared__ __align__(16) float Bs[BK][BN];

    const int tid = threadIdx.x;
    const int tx  = tid % TX;
    const int ty  = tid / TX;
    const int m0  = blockIdx.y * BM;
    const int n0  = blockIdx.x * BN;

    unsigned long long acc[TM / 2][TN];
#pragma unroll
    for (int i = 0; i < TM / 2; i++)
#pragma unroll
        for (int j = 0; j < TN; j++) acc[i][j] = 0ULL;

    const float* Abase = A + (size_t)m0 * lda;
    const float* Bbase = Bw + n0;
    const int nk = K / BK;

    for (int kb = 0; kb < nk; kb++) {
        // Load A tile (BMxBK), store transposed As[k][m]
#pragma unroll
        for (int i = 0; i < AF4; i++) {
            int f   = tid + i * THREADS;
            int row = f / (BK / 4);
            int c4  = f % (BK / 4);
            float4 v = *(const float4*)(Abase + (size_t)row * lda + kb * BK + c4 * 4);
            As[c4 * 4 + 0][row] = v.x;
            As[c4 * 4 + 1][row] = v.y;
            As[c4 * 4 + 2][row] = v.z;
            As[c4 * 4 + 3][row] = v.w;
        }
        // Load B tile (BKxBN) straight
#pragma unroll
        for (int i = 0; i < BF4; i++) {
            int f   = tid + i * THREADS;
            int row = f / (BN / 4);
            int c4  = f % (BN / 4);
            *(float4*)&Bs[row][c4 * 4] =
                *(const float4*)(Bbase + (size_t)(kb * BK + row) * ldb + c4 * 4);
        }
        __syncthreads();

#pragma unroll
        for (int k = 0; k < BK; k++) {
            unsigned long long a2[TM / 2];
#pragma unroll
            for (int i = 0; i < TM / 2; i++)
                a2[i] = *(const unsigned long long*)&As[k][ty * TM + 2 * i];

            float bv[TN];
#pragma unroll
            for (int j4 = 0; j4 < TN / 4; j4++) {
                float4 b4 = *(const float4*)&Bs[k][tx * TN + j4 * 4];
                bv[j4 * 4 + 0] = b4.x; bv[j4 * 4 + 1] = b4.y;
                bv[j4 * 4 + 2] = b4.z; bv[j4 * 4 + 3] = b4.w;
            }
#pragma unroll
            for (int j = 0; j < TN; j++) {
                unsigned long long bp = pack2(bv[j]);
#pragma unroll
                for (int i = 0; i < TM / 2; i++) ffma2(acc[i][j], a2[i], bp);
            }
        }
        __syncthreads();
    }

    // Epilogue
#pragma unroll
    for (int i = 0; i < TM / 2; i++) {
#pragma unroll
        for (int j = 0; j < TN; j++) {
            int m   = m0 + ty * TM + 2 * i;
            int col = n0 + tx * TN + j;
            float v0, v1;
            unpack2(acc[i][j], v0, v1);
            epi_store<EPI>(m,     col, v0, C0, C1, bias, aux, ldc);
            epi_store<EPI>(m + 1, col, v1, C0, C1, bias, aux, ldc);
        }
    }
}

// ---------------------------------------------------------------------------
// Pad x_proj_w (768x112) -> g_xpw (768x128, zeros in pad cols)
// ---------------------------------------------------------------------------
__global__ void pad_w_kernel(const float* __restrict__ w) {
    int idx = blockIdx.x * blockDim.x + threadIdx.x;
    if (idx >= cD * XPN) return;
    int r = idx / XPN, c = idx % XPN;
    g_xpw[idx] = (c < XPW) ? w[r * XPW + c] : 0.0f;
}

// ---------------------------------------------------------------------------
// Sequential scan. Cartesian reformulation:
//   scale1 = mag^(e-1) = exp2( 0.25*(1-alpha) * log2(h0^2+h1^2+1e-8) )
//   h = scale1*h + Bn * (x*dt)
//   scale2 = tanh(m2)/m2
//   h *= scale2 ;  y = sum_n (C0*h0 + C1*h1)
// grid (cD/8, cB), block 128: thread = (d_local:8) x (n:16). State in regs.
// Distance-2 load prefetch hides L2 latency off the recurrence chain.
// ---------------------------------------------------------------------------
__global__ __launch_bounds__(128)
void scan_kernel(const float* __restrict__ A_log) {
    const int b = blockIdx.y;
    const int n = threadIdx.x & 15;
    const int d = blockIdx.x * 8 + (threadIdx.x >> 4);

    const float Aneg = -__expf(A_log[n]);
    const float ph = (float)n * 0.39269908169872414f;  // n * pi/8
    float h0 = 0.01f * cosf(ph);
    float h1 = 0.01f * sinf(ph);

    const size_t iD = (size_t)b * cL * cD + d;
    const size_t iP = (size_t)b * cL * XPN;

    struct In { float dtv, xv, zv; float2 Bn, Cn; };
    auto LOAD = [&](int t) -> In {
        In r;
        size_t jD = iD + (size_t)t * cD;
        size_t jP = iP + (size_t)t * XPN;
        r.dtv = g_dt[jD];
        r.xv  = g_xdt[jD];
        r.zv  = g_zg[jD];
        r.Bn  = *(const float2*)&g_xp[jP + cR + 2 * n];
        r.Cn  = *(const float2*)&g_xp[jP + cR + 2 * cN + 2 * n];
        return r;
    };

    In pre[2];
    pre[0] = LOAD(0);
    pre[1] = LOAD(1);

    for (int t = 0; t < cL; t++) {
        In cur = pre[t & 1];
        if (t + 2 < cL) pre[t & 1] = LOAD(t + 2);

        float alpha;
        asm("ex2.approx.f32 %0, %1;" : "=f"(alpha)
            : "f"(cur.dtv * Aneg * 1.4426950408889634f));

        float r2 = fmaf(h0, h0, fmaf(h1, h1, 1e-8f));
        float lg;
        asm("lg2.approx.f32 %0, %1;" : "=f"(lg) : "f"(r2));
        float s1;
        asm("ex2.approx.f32 %0, %1;" : "=f"(s1) : "f"(0.25f * (1.0f - alpha) * lg));

        h0 = fmaf(s1, h0, cur.Bn.x * cur.xv);
        h1 = fmaf(s1, h1, cur.Bn.y * cur.xv);

        float r2b = fmaf(h0, h0, fmaf(h1, h1, 1e-8f));
        float inv = rsqrtf(r2b);
        float m2  = r2b * inv;
        float th;
        asm("tanh.approx.f32 %0, %1;" : "=f"(th) : "f"(m2));
        float sc = th * inv;
        h0 *= sc;
        h1 *= sc;

        float yv = fmaf(h0, cur.Cn.x, h1 * cur.Cn.y);
        yv += __shfl_xor_sync(0xffffffffu, yv, 1);
        yv += __shfl_xor_sync(0xffffffffu, yv, 2);
        yv += __shfl_xor_sync(0xffffffffu, yv, 4);
        yv += __shfl_xor_sync(0xffffffffu, yv, 8);
        if (n == 0) g_yg[iD + (size_t)t * cD] = yv * cur.zv;
    }
}

// ---------------------------------------------------------------------------
// kernel_launch
// inputs: x, in_proj_w, x_proj_w, dt_proj_w, dt_proj_b, out_proj_w, out_proj_b, A_log
// ---------------------------------------------------------------------------
extern "C" void kernel_launch(void* const* d_in, const int* in_sizes, int n_in,
                              void* d_out, int out_size) {
    const float* x     = (const float*)d_in[0];
    const float* w_in  = (const float*)d_in[1];
    const float* w_xp  = (const float*)d_in[2];
    const float* w_dt  = (const float*)d_in[3];
    const float* b_dt  = (const float*)d_in[4];
    const float* w_o   = (const float*)d_in[5];
    const float* b_o   = (const float*)d_in[6];
    const float* A_log = (const float*)d_in[7];
    float* out = (float*)d_out;

    float *p_xin, *p_zg, *p_xpw, *p_xp, *p_dt, *p_xdt, *p_yg;
    cudaGetSymbolAddress((void**)&p_xin, g_xin);
    cudaGetSymbolAddress((void**)&p_zg,  g_zg);
    cudaGetSymbolAddress((void**)&p_xpw, g_xpw);
    cudaGetSymbolAddress((void**)&p_xp,  g_xp);
    cudaGetSymbolAddress((void**)&p_dt,  g_dt);
    cudaGetSymbolAddress((void**)&p_xdt, g_xdt);
    cudaGetSymbolAddress((void**)&p_yg,  g_yg);

    // 0) pad x_proj_w to 128 cols
    pad_w_kernel<<<(cD * XPN + 255) / 256, 256>>>(w_xp);

    // 1) in_proj: xz = x @ w_in ; xin = silu(xz[:, :D]) ; zg = silu(xz[:, D:])
    gemm_kernel<128, 128, 16, 8, 8, 0>
        <<<dim3((2 * cD) / 128, cM / 128), 256>>>(
            x, w_in, p_xin, p_zg, nullptr, nullptr, cD, cD, 2 * cD, 0);

    // 2) x_proj: xp = xin @ xpw_pad  (M x 128)
    gemm_kernel<32, 128, 32, 4, 4, 1>
        <<<dim3(1, cM / 32), 256>>>(
            p_xin, p_xpw, p_xp, nullptr, nullptr, nullptr, cD, cD, XPN, XPN);

    // 3) dt_proj: dt = softplus(xp[:, :48] @ w_dt + b_dt) ; xdt = dt * xin
    gemm_kernel<128, 128, 16, 8, 8, 2>
        <<<dim3(cD / 128, cM / 128), 256>>>(
            p_xp, w_dt, p_dt, p_xdt, b_dt, p_xin, cR, XPN, cD, 0);

    // 4) recurrent scan -> yg = ys * silu(z)
    scan_kernel<<<dim3(cD / 8, cB), 128>>>(A_log);

    // 5) out_proj: out = yg @ w_o + b_o
    gemm_kernel<128, 128, 16, 8, 8, 3>
        <<<dim3(cD / 128, cM / 128), 256>>>(
            p_yg, w_o, out, nullptr, b_o, nullptr, cD, cD, cD, cD);
}

// round 13
// speedup vs baseline: 1.6330x; 1.6330x over previous
#include <cuda_runtime.h>
#include <cstdint>
#include <cstddef>

// ---------------------------------------------------------------------------
// Problem constants
// ---------------------------------------------------------------------------
constexpr int cB = 4;
constexpr int cL = 1024;
constexpr int cD = 768;
constexpr int cN = 16;
constexpr int cR = 48;
constexpr int cM = cB * cL;          // 4096 rows
constexpr int XPW = cR + 4 * cN;     // 112 true x_proj width
constexpr int XPN = 128;             // padded x_proj width
constexpr int DTK = 64;              // padded dt_proj K (48 -> 64)

// ---------------------------------------------------------------------------
// Scratch (static device globals — no allocation)
// ---------------------------------------------------------------------------
__device__ float g_xin [cM * cD];       // silu(xz[:, :D])
__device__ float g_zg  [cM * cD];       // silu(xz[:, D:])
__device__ float g_xp  [cM * XPN];      // x_in @ x_proj_w (cols 112..127 = 0)
__device__ float g_dt  [cM * cD];       // softplus(dt_pre)
__device__ float g_xdt [cM * cD];       // dt * x_in
__device__ float g_yg  [cM * cD];       // ys * silu(z)
__device__ float g_winT[2 * cD * cD];   // in_proj_w^T   [1536][768]
__device__ float g_wxpT[XPN * cD];      // x_proj_w^T    [128][768] (rows 112.. = 0)
__device__ float g_wdtT[cD * DTK];      // dt_proj_w^T   [768][64]  (cols 48.. = 0)
__device__ float g_woT [cD * cD];       // out_proj_w^T  [768][768]

// ---------------------------------------------------------------------------
// Helpers
// ---------------------------------------------------------------------------
__device__ __forceinline__ float cvt_tf32(float x) {
    float y;
    asm("cvt.rna.tf32.f32 %0, %1;" : "=f"(y) : "f"(x));
    return y;
}
__device__ __forceinline__ float siluf(float x) { return x / (1.0f + __expf(-x)); }
__device__ __forceinline__ float softplusf(float x) {
    return fmaxf(x, 0.0f) + log1pf(__expf(-fabsf(x)));
}

// m16n8k8 tf32 mma (sm_80+ portable PTX; runs on Blackwell tensor cores)
__device__ __forceinline__ void mma_tf32(float& c0, float& c1, float& c2, float& c3,
                                         uint32_t a0, uint32_t a1, uint32_t a2, uint32_t a3,
                                         uint32_t b0, uint32_t b1) {
    asm volatile(
        "mma.sync.aligned.m16n8k8.row.col.f32.tf32.tf32.f32 "
        "{%0,%1,%2,%3}, {%4,%5,%6,%7}, {%8,%9}, {%0,%1,%2,%3};"
        : "+f"(c0), "+f"(c1), "+f"(c2), "+f"(c3)
        : "r"(a0), "r"(a1), "r"(a2), "r"(a3), "r"(b0), "r"(b1));
}

// ---------------------------------------------------------------------------
// Epilogues
//  0: split-silu (in_proj)  1: plain (x_proj)  2: softplus+x*dt (dt_proj)  3: bias
// ---------------------------------------------------------------------------
template<int EPI>
__device__ __forceinline__ void epi_store(int m, int col, float v,
                                          float* C0, float* C1,
                                          const float* bias, const float* aux,
                                          int ldc) {
    if constexpr (EPI == 0) {
        float s = siluf(v);
        if (col < cD) C0[(size_t)m * cD + col] = s;
        else          C1[(size_t)m * cD + (col - cD)] = s;
    } else if constexpr (EPI == 1) {
        C0[(size_t)m * ldc + col] = v;
    } else if constexpr (EPI == 2) {
        float dtv = softplusf(v + bias[col]);
        size_t idx = (size_t)m * cD + col;
        C0[idx] = dtv;
        C1[idx] = dtv * aux[idx];
    } else {
        C0[(size_t)m * ldc + col] = v + bias[col];
    }
}

// ---------------------------------------------------------------------------
// Tensor-core tf32 GEMM: C[M,N] = A[M,K](lda) @ Bw^T, Bw = [N][K] row-major.
// CTA tile 128x128, 256 threads = 8 warps (4 m x 2 n), warp tile 32x64.
// BK = 32. Smem layout [row][36] (pad 4): coalesced LDG.128, conflict-free
// STS.128 and conflict-free fragment LDS.32 (bank = 4g+t bijective).
// ---------------------------------------------------------------------------
template<int EPI>
__global__ void __launch_bounds__(256, 2) gemm_mma(
    const float* __restrict__ A, const float* __restrict__ Bw,
    float* __restrict__ C0, float* __restrict__ C1,
    const float* __restrict__ bias, const float* __restrict__ aux,
    int K, int lda, int ldc)
{
    __shared__ float As[128][36];
    __shared__ float Bs[128][36];

    const int tid  = threadIdx.x;
    const int wid  = tid >> 5;
    const int lane = tid & 31;
    const int g    = lane >> 2;      // group 0..7
    const int t    = lane & 3;       // thread-in-group 0..3
    const int mw   = (wid & 3) * 32; // warp m offset in tile
    const int nw   = (wid >> 2) * 64;// warp n offset in tile
    const int m0   = blockIdx.y * 128;
    const int n0   = blockIdx.x * 128;

    float c[2][8][4];
#pragma unroll
    for (int im = 0; im < 2; im++)
#pragma unroll
        for (int in_ = 0; in_ < 8; in_++)
#pragma unroll
            for (int r = 0; r < 4; r++) c[im][in_][r] = 0.0f;

    const float* Ab = A  + (size_t)m0 * lda;
    const float* Bb = Bw + (size_t)n0 * K;
    const int nk = K / 32;

    float4 pa[4], pb[4];
    // prefetch chunk 0 (coalesced: 8 lanes cover one 128B row segment)
#pragma unroll
    for (int i = 0; i < 4; i++) {
        int f = tid + i * 256;
        int r = f >> 3, q = f & 7;
        pa[i] = *(const float4*)(Ab + (size_t)r * lda + q * 4);
        pb[i] = *(const float4*)(Bb + (size_t)r * K   + q * 4);
    }

    for (int kb = 0; kb < nk; kb++) {
        if (kb) __syncthreads();     // previous chunk's compute done
        // store prefetched chunk to smem with tf32 rounding
#pragma unroll
        for (int i = 0; i < 4; i++) {
            int f = tid + i * 256;
            int r = f >> 3, q = f & 7;
            float4 va = pa[i], vb = pb[i];
            va.x = cvt_tf32(va.x); va.y = cvt_tf32(va.y);
            va.z = cvt_tf32(va.z); va.w = cvt_tf32(va.w);
            vb.x = cvt_tf32(vb.x); vb.y = cvt_tf32(vb.y);
            vb.z = cvt_tf32(vb.z); vb.w = cvt_tf32(vb.w);
            *(float4*)&As[r][q * 4] = va;
            *(float4*)&Bs[r][q * 4] = vb;
        }
        __syncthreads();

        // prefetch next chunk (lands under the mma work below)
        if (kb + 1 < nk) {
            const float* An = Ab + (size_t)(kb + 1) * 32;
            const float* Bn = Bb + (size_t)(kb + 1) * 32;
#pragma unroll
            for (int i = 0; i < 4; i++) {
                int f = tid + i * 256;
                int r = f >> 3, q = f & 7;
                pa[i] = *(const float4*)(An + (size_t)r * lda + q * 4);
                pb[i] = *(const float4*)(Bn + (size_t)r * K   + q * 4);
            }
        }

        // 4 k8-steps of m16n8k8
#pragma unroll
        for (int ks = 0; ks < 4; ks++) {
            const int k8 = ks * 8;
            uint32_t a[2][4];
#pragma unroll
            for (int im = 0; im < 2; im++) {
                const int mr = mw + im * 16;
                a[im][0] = __float_as_uint(As[mr + g    ][k8 + t    ]);
                a[im][1] = __float_as_uint(As[mr + g + 8][k8 + t    ]);
                a[im][2] = __float_as_uint(As[mr + g    ][k8 + t + 4]);
                a[im][3] = __float_as_uint(As[mr + g + 8][k8 + t + 4]);
            }
#pragma unroll
            for (int in_ = 0; in_ < 8; in_++) {
                const int nc = nw + in_ * 8;
                uint32_t b0 = __float_as_uint(Bs[nc + g][k8 + t    ]);
                uint32_t b1 = __float_as_uint(Bs[nc + g][k8 + t + 4]);
#pragma unroll
                for (int im = 0; im < 2; im++)
                    mma_tf32(c[im][in_][0], c[im][in_][1], c[im][in_][2], c[im][in_][3],
                             a[im][0], a[im][1], a[im][2], a[im][3], b0, b1);
            }
        }
    }

    // Epilogue: c0:(g, 2t) c1:(g, 2t+1) c2:(g+8, 2t) c3:(g+8, 2t+1)
#pragma unroll
    for (int im = 0; im < 2; im++) {
        const int row0 = m0 + mw + im * 16 + g;
#pragma unroll
        for (int in_ = 0; in_ < 8; in_++) {
            const int col0 = n0 + nw + in_ * 8 + 2 * t;
            epi_store<EPI>(row0,     col0,     c[im][in_][0], C0, C1, bias, aux, ldc);
            epi_store<EPI>(row0,     col0 + 1, c[im][in_][1], C0, C1, bias, aux, ldc);
            epi_store<EPI>(row0 + 8, col0,     c[im][in_][2], C0, C1, bias, aux, ldc);
            epi_store<EPI>(row0 + 8, col0 + 1, c[im][in_][3], C0, C1, bias, aux, ldc);
        }
    }
}

// ---------------------------------------------------------------------------
// Transpose + pad: dst[Np][Kp] = src[k][n] (src row-major [Ks][Ns]), 0-padded.
// ---------------------------------------------------------------------------
__global__ void transpose_pad(const float* __restrict__ src, float* __restrict__ dst,
                              int Ks, int Ns, int Kp, int Np) {
    __shared__ float tsm[32][33];
    int nb = blockIdx.x * 32, kb = blockIdx.y * 32;
#pragma unroll
    for (int i = threadIdx.y; i < 32; i += 8) {
        int k = kb + i, n = nb + threadIdx.x;
        tsm[i][threadIdx.x] = (k < Ks && n < Ns) ? src[(size_t)k * Ns + n] : 0.0f;
    }
    __syncthreads();
#pragma unroll
    for (int i = threadIdx.y; i < 32; i += 8) {
        int n = nb + i, k = kb + threadIdx.x;
        if (n < Np && k < Kp) dst[(size_t)n * Kp + k] = tsm[threadIdx.x][i];
    }
}

// ---------------------------------------------------------------------------
// Sequential scan (proven: rel_err 3.6e-6 in fp32 pipeline)
// ---------------------------------------------------------------------------
__global__ __launch_bounds__(128)
void scan_kernel(const float* __restrict__ A_log) {
    const int b = blockIdx.y;
    const int n = threadIdx.x & 15;
    const int d = blockIdx.x * 8 + (threadIdx.x >> 4);

    const float Aneg = -__expf(A_log[n]);
    const float ph = (float)n * 0.39269908169872414f;
    float h0 = 0.01f * cosf(ph);
    float h1 = 0.01f * sinf(ph);

    const size_t iD = (size_t)b * cL * cD + d;
    const size_t iP = (size_t)b * cL * XPN;

    struct In { float dtv, xv, zv; float2 Bn, Cn; };
    auto LOAD = [&](int t) -> In {
        In r;
        size_t jD = iD + (size_t)t * cD;
        size_t jP = iP + (size_t)t * XPN;
        r.dtv = g_dt[jD];
        r.xv  = g_xdt[jD];
        r.zv  = g_zg[jD];
        r.Bn  = *(const float2*)&g_xp[jP + cR + 2 * n];
        r.Cn  = *(const float2*)&g_xp[jP + cR + 2 * cN + 2 * n];
        return r;
    };

    In pre[2];
    pre[0] = LOAD(0);
    pre[1] = LOAD(1);

    for (int t = 0; t < cL; t++) {
        In cur = pre[t & 1];
        if (t + 2 < cL) pre[t & 1] = LOAD(t + 2);

        float alpha;
        asm("ex2.approx.f32 %0, %1;" : "=f"(alpha)
            : "f"(cur.dtv * Aneg * 1.4426950408889634f));

        float r2 = fmaf(h0, h0, fmaf(h1, h1, 1e-8f));
        float lg;
        asm("lg2.approx.f32 %0, %1;" : "=f"(lg) : "f"(r2));
        float s1;
        asm("ex2.approx.f32 %0, %1;" : "=f"(s1) : "f"(0.25f * (1.0f - alpha) * lg));

        h0 = fmaf(s1, h0, cur.Bn.x * cur.xv);
        h1 = fmaf(s1, h1, cur.Bn.y * cur.xv);

        float r2b = fmaf(h0, h0, fmaf(h1, h1, 1e-8f));
        float inv = rsqrtf(r2b);
        float m2  = r2b * inv;
        float th;
        asm("tanh.approx.f32 %0, %1;" : "=f"(th) : "f"(m2));
        float sc = th * inv;
        h0 *= sc;
        h1 *= sc;

        float yv = fmaf(h0, cur.Cn.x, h1 * cur.Cn.y);
        yv += __shfl_xor_sync(0xffffffffu, yv, 1);
        yv += __shfl_xor_sync(0xffffffffu, yv, 2);
        yv += __shfl_xor_sync(0xffffffffu, yv, 4);
        yv += __shfl_xor_sync(0xffffffffu, yv, 8);
        if (n == 0) g_yg[iD + (size_t)t * cD] = yv * cur.zv;
    }
}

// ---------------------------------------------------------------------------
// kernel_launch
// inputs: x, in_proj_w, x_proj_w, dt_proj_w, dt_proj_b, out_proj_w, out_proj_b, A_log
// ---------------------------------------------------------------------------
extern "C" void kernel_launch(void* const* d_in, const int* in_sizes, int n_in,
                              void* d_out, int out_size) {
    const float* x     = (const float*)d_in[0];
    const float* w_in  = (const float*)d_in[1];
    const float* w_xp  = (const float*)d_in[2];
    const float* w_dt  = (const float*)d_in[3];
    const float* b_dt  = (const float*)d_in[4];
    const float* b_o   = (const float*)d_in[6];
    const float* w_o   = (const float*)d_in[5];
    const float* A_log = (const float*)d_in[7];
    float* out = (float*)d_out;

    float *p_xin, *p_zg, *p_xp, *p_dt, *p_xdt, *p_yg;
    float *p_winT, *p_wxpT, *p_wdtT, *p_woT;
    cudaGetSymbolAddress((void**)&p_xin,  g_xin);
    cudaGetSymbolAddress((void**)&p_zg,   g_zg);
    cudaGetSymbolAddress((void**)&p_xp,   g_xp);
    cudaGetSymbolAddress((void**)&p_dt,   g_dt);
    cudaGetSymbolAddress((void**)&p_xdt,  g_xdt);
    cudaGetSymbolAddress((void**)&p_yg,   g_yg);
    cudaGetSymbolAddress((void**)&p_winT, g_winT);
    cudaGetSymbolAddress((void**)&p_wxpT, g_wxpT);
    cudaGetSymbolAddress((void**)&p_wdtT, g_wdtT);
    cudaGetSymbolAddress((void**)&p_woT,  g_woT);

    dim3 tb(32, 8);
    // 0) transpose + pad all weights to [N][K]
    transpose_pad<<<dim3(48, 24), tb>>>(w_in, p_winT, cD, 2 * cD, cD, 2 * cD);
    transpose_pad<<<dim3( 4, 24), tb>>>(w_xp, p_wxpT, cD, XPW,   cD, XPN);
    transpose_pad<<<dim3(24,  2), tb>>>(w_dt, p_wdtT, cR, cD,    DTK, cD);
    transpose_pad<<<dim3(24, 24), tb>>>(w_o,  p_woT,  cD, cD,    cD, cD);

    // 1) in_proj: xin = silu(x@w[:, :D]), zg = silu(x@w[:, D:])
    gemm_mma<0><<<dim3(12, 32), 256>>>(
        x, p_winT, p_xin, p_zg, nullptr, nullptr, cD, cD, 0);

    // 2) x_proj: xp = xin @ xpw (M x 128, cols 112..127 = 0 via zero weights)
    gemm_mma<1><<<dim3(1, 32), 256>>>(
        p_xin, p_wxpT, p_xp, nullptr, nullptr, nullptr, cD, cD, XPN);

    // 3) dt_proj (K padded to 64; weight cols 48..63 zero nullify xp B/C cols):
    //    dt = softplus(xp[:, :48]@w_dt + b); xdt = dt*xin
    gemm_mma<2><<<dim3(6, 32), 256>>>(
        p_xp, p_wdtT, p_dt, p_xdt, b_dt, p_xin, DTK, XPN, 0);

    // 4) recurrent scan -> yg = ys * silu(z)
    scan_kernel<<<dim3(cD / 8, cB), 128>>>(A_log);

    // 5) out_proj: out = yg @ w_o + b_o
    gemm_mma<3><<<dim3(6, 32), 256>>>(
        p_yg, p_woT, out, nullptr, b_o, nullptr, cD, cD, cD);
}

// round 14
// speedup vs baseline: 1.8179x; 1.1132x over previous
#include <cuda_runtime.h>
#include <cuda_fp16.h>
#include <cstdint>
#include <cstddef>

// ---------------------------------------------------------------------------
// Problem constants
// ---------------------------------------------------------------------------
constexpr int cB = 4;
constexpr int cL = 1024;
constexpr int cD = 768;
constexpr int cN = 16;
constexpr int cR = 48;
constexpr int cM = cB * cL;          // 4096 rows
constexpr int XPW = cR + 4 * cN;     // 112 true x_proj width
constexpr int XPN = 128;             // padded x_proj width
constexpr int DTK = 64;              // padded dt_proj K (48 -> 64)

// ---------------------------------------------------------------------------
// Scratch (static device globals — no allocation)
// ---------------------------------------------------------------------------
__device__ float  g_xin [cM * cD];      // silu(xz[:, :D])
__device__ float  g_zg  [cM * cD];      // silu(xz[:, D:])
__device__ float  g_xp  [cM * XPN];     // x_in @ x_proj_w (cols 112..127 = 0)
__device__ float  g_dt  [cM * cD];      // softplus(dt_pre)
__device__ float  g_xdt [cM * cD];      // dt * x_in
__device__ float  g_yg  [cM * cD];      // ys * silu(z)
__device__ __half g_winT[2 * cD * cD];  // in_proj_w^T   [1536][768] half
__device__ __half g_wxpT[XPN * cD];     // x_proj_w^T    [128][768]  (rows 112.. = 0)
__device__ __half g_wdtT[cD * DTK];     // dt_proj_w^T   [768][64]   (cols 48.. = 0)
__device__ __half g_woT [cD * cD];      // out_proj_w^T  [768][768]

// ---------------------------------------------------------------------------
// Helpers
// ---------------------------------------------------------------------------
__device__ __forceinline__ uint32_t smem_u32(const void* p) {
    uint32_t a;
    asm("{ .reg .u64 t; cvta.to.shared.u64 t, %1; cvt.u32.u64 %0, t; }"
        : "=r"(a) : "l"(p));
    return a;
}
__device__ __forceinline__ float siluf(float x) { return x / (1.0f + __expf(-x)); }
__device__ __forceinline__ float softplusf(float x) {
    return fmaxf(x, 0.0f) + log1pf(__expf(-fabsf(x)));
}

// fp16 m16n8k16 mma with fp32 accumulate (sm_80+ portable; Blackwell HMMA)
__device__ __forceinline__ void mma_f16(float* c, const uint32_t* a, const uint32_t* b) {
    asm volatile(
        "mma.sync.aligned.m16n8k16.row.col.f32.f16.f16.f32 "
        "{%0,%1,%2,%3}, {%4,%5,%6,%7}, {%8,%9}, {%0,%1,%2,%3};"
        : "+f"(c[0]), "+f"(c[1]), "+f"(c[2]), "+f"(c[3])
        : "r"(a[0]), "r"(a[1]), "r"(a[2]), "r"(a[3]), "r"(b[0]), "r"(b[1]));
}
__device__ __forceinline__ void ldm_x4(uint32_t* r, uint32_t addr) {
    asm volatile("ldmatrix.sync.aligned.m8n8.x4.shared.b16 {%0,%1,%2,%3}, [%4];"
                 : "=r"(r[0]), "=r"(r[1]), "=r"(r[2]), "=r"(r[3]) : "r"(addr));
}
__device__ __forceinline__ void ldm_x2(uint32_t* r, uint32_t addr) {
    asm volatile("ldmatrix.sync.aligned.m8n8.x2.shared.b16 {%0,%1}, [%2];"
                 : "=r"(r[0]), "=r"(r[1]) : "r"(addr));
}

// ---------------------------------------------------------------------------
// Epilogues
//  0: split-silu (in_proj)  1: plain (x_proj)  2: softplus+x*dt (dt_proj)  3: bias
// ---------------------------------------------------------------------------
template<int EPI>
__device__ __forceinline__ void epi_store(int m, int col, float v,
                                          float* C0, float* C1,
                                          const float* bias, const float* aux,
                                          int ldc) {
    if constexpr (EPI == 0) {
        float s = siluf(v);
        if (col < cD) C0[(size_t)m * cD + col] = s;
        else          C1[(size_t)m * cD + (col - cD)] = s;
    } else if constexpr (EPI == 1) {
        C0[(size_t)m * ldc + col] = v;
    } else if constexpr (EPI == 2) {
        float dtv = softplusf(v + bias[col]);
        size_t idx = (size_t)m * cD + col;
        C0[idx] = dtv;
        C1[idx] = dtv * aux[idx];
    } else {
        C0[(size_t)m * ldc + col] = v + bias[col];
    }
}

// ---------------------------------------------------------------------------
// fp16 tensor-core GEMM: C[M,N] = A[M,K](fp32,lda) @ Bw^T, Bw = half [N][K].
// CTA tile 128x128, 256 threads = 8 warps (2m x 4n), warp tile 64x32.
// BK = 32. Smem half[128][40]: 80B row stride -> 16B-aligned ldmatrix rows,
// conflict-free ldmatrix phases (banks (20r+4c) mod 32 distinct over 8 rows).
// ---------------------------------------------------------------------------
template<int EPI>
__global__ void __launch_bounds__(256, 2) gemm_h(
    const float* __restrict__ A, const __half* __restrict__ Bw,
    float* __restrict__ C0, float* __restrict__ C1,
    const float* __restrict__ bias, const float* __restrict__ aux,
    int K, int lda, int ldc)
{
    __shared__ __align__(16) __half As[128][40];
    __shared__ __align__(16) __half Bs[128][40];

    const int tid  = threadIdx.x;
    const int wid  = tid >> 5;
    const int lane = tid & 31;
    const int g    = lane >> 2;
    const int t    = lane & 3;
    const int mw   = (wid & 1) * 64;   // warp m offset (2 m-groups)
    const int nw   = (wid >> 1) * 32;  // warp n offset (4 n-groups)
    const int m0   = blockIdx.y * 128;
    const int n0   = blockIdx.x * 128;

    float c[4][4][4];                  // [im 0..3][in 0..3][4]
#pragma unroll
    for (int im = 0; im < 4; im++)
#pragma unroll
        for (int in_ = 0; in_ < 4; in_++)
#pragma unroll
            for (int r = 0; r < 4; r++) c[im][in_][r] = 0.0f;

    // ldmatrix per-lane row addressing
    const uint32_t sbA = smem_u32(&As[0][0]);
    const uint32_t sbB = smem_u32(&Bs[0][0]);
    const int aRow = mw + (lane & 15);
    const int aK   = (lane >> 4) * 8;          // k+8 for matrices 2,3
    const int bRow = nw + (lane & 7);
    const int bK   = ((lane >> 3) & 1) * 8;    // k+8 for matrix 1

    const float*  Ab = A  + (size_t)m0 * lda;
    const __half* Bb = Bw + (size_t)n0 * K;
    const int nk = K / 32;

    float4 pa[4];
    uint4  pb[2];
    // prefetch chunk 0 (A: 128x32 fp32 = 1024 float4; B: 128x32 half = 512 uint4)
#pragma unroll
    for (int i = 0; i < 4; i++) {
        int f = tid + i * 256, r = f >> 3, q = f & 7;
        pa[i] = *(const float4*)(Ab + (size_t)r * lda + q * 4);
    }
#pragma unroll
    for (int i = 0; i < 2; i++) {
        int f = tid + i * 256, r = f >> 2, q = f & 3;
        pb[i] = *(const uint4*)(Bb + (size_t)r * K + q * 8);
    }

    for (int kb = 0; kb < nk; kb++) {
        if (kb) __syncthreads();
        // store prefetched chunk (A converted fp32 -> half)
#pragma unroll
        for (int i = 0; i < 4; i++) {
            int f = tid + i * 256, r = f >> 3, q = f & 7;
            __half2 h0 = __floats2half2_rn(pa[i].x, pa[i].y);
            __half2 h1 = __floats2half2_rn(pa[i].z, pa[i].w);
            uint2 u;
            u.x = *reinterpret_cast<uint32_t*>(&h0);
            u.y = *reinterpret_cast<uint32_t*>(&h1);
            *(uint2*)&As[r][q * 4] = u;
        }
#pragma unroll
        for (int i = 0; i < 2; i++) {
            int f = tid + i * 256, r = f >> 2, q = f & 3;
            *(uint4*)&Bs[r][q * 8] = pb[i];
        }
        __syncthreads();

        // prefetch next chunk under the mma work
        if (kb + 1 < nk) {
            const float*  An = Ab + (size_t)(kb + 1) * 32;
            const __half* Bn = Bb + (size_t)(kb + 1) * 32;
#pragma unroll
            for (int i = 0; i < 4; i++) {
                int f = tid + i * 256, r = f >> 3, q = f & 7;
                pa[i] = *(const float4*)(An + (size_t)r * lda + q * 4);
            }
#pragma unroll
            for (int i = 0; i < 2; i++) {
                int f = tid + i * 256, r = f >> 2, q = f & 3;
                pb[i] = *(const uint4*)(Bn + (size_t)r * K + q * 8);
            }
        }

        // 2 k16-steps per chunk
#pragma unroll
        for (int ks = 0; ks < 2; ks++) {
            uint32_t af[4][4];
#pragma unroll
            for (int im = 0; im < 4; im++)
                ldm_x4(af[im], sbA + ((aRow + im * 16) * 40 + ks * 16 + aK) * 2);
            uint32_t bf[4][2];
#pragma unroll
            for (int in_ = 0; in_ < 4; in_++)
                ldm_x2(bf[in_], sbB + ((bRow + in_ * 8) * 40 + ks * 16 + bK) * 2);
#pragma unroll
            for (int in_ = 0; in_ < 4; in_++)
#pragma unroll
                for (int im = 0; im < 4; im++)
                    mma_f16(c[im][in_], af[im], bf[in_]);
        }
    }

    // Epilogue: c0:(g,2t) c1:(g,2t+1) c2:(g+8,2t) c3:(g+8,2t+1)
#pragma unroll
    for (int im = 0; im < 4; im++) {
        const int row0 = m0 + mw + im * 16 + g;
#pragma unroll
        for (int in_ = 0; in_ < 4; in_++) {
            const int col0 = n0 + nw + in_ * 8 + 2 * t;
            epi_store<EPI>(row0,     col0,     c[im][in_][0], C0, C1, bias, aux, ldc);
            epi_store<EPI>(row0,     col0 + 1, c[im][in_][1], C0, C1, bias, aux, ldc);
            epi_store<EPI>(row0 + 8, col0,     c[im][in_][2], C0, C1, bias, aux, ldc);
            epi_store<EPI>(row0 + 8, col0 + 1, c[im][in_][3], C0, C1, bias, aux, ldc);
        }
    }
}

// ---------------------------------------------------------------------------
// Transpose + pad + convert to half: dst[Np][Kp] = half(src[k][n]), 0-padded.
// ---------------------------------------------------------------------------
__global__ void transpose_pad_h(const float* __restrict__ src, __half* __restrict__ dst,
                                int Ks, int Ns, int Kp, int Np) {
    __shared__ float tsm[32][33];
    int nb = blockIdx.x * 32, kb = blockIdx.y * 32;
#pragma unroll
    for (int i = threadIdx.y; i < 32; i += 8) {
        int k = kb + i, n = nb + threadIdx.x;
        tsm[i][threadIdx.x] = (k < Ks && n < Ns) ? src[(size_t)k * Ns + n] : 0.0f;
    }
    __syncthreads();
#pragma unroll
    for (int i = threadIdx.y; i < 32; i += 8) {
        int n = nb + i, k = kb + threadIdx.x;
        if (n < Np && k < Kp) dst[(size_t)n * Kp + k] = __float2half_rn(tsm[threadIdx.x][i]);
    }
}

// ---------------------------------------------------------------------------
// Sequential scan. Chain shortened vs R13 by carrying lgm2 = log2(|h|^2+eps):
// the lg2 sits on a side branch off tanh instead of between h and ex2.
// Semantics identical: s1 = exp2(q * lgm2), q = 0.25*(1-alpha).
// ---------------------------------------------------------------------------
__global__ __launch_bounds__(128)
void scan_kernel(const float* __restrict__ A_log) {
    const int b = blockIdx.y;
    const int n = threadIdx.x & 15;
    const int d = blockIdx.x * 8 + (threadIdx.x >> 4);

    const float Aneg = -__expf(A_log[n]);
    const float ph = (float)n * 0.39269908169872414f;
    float h0 = 0.01f * cosf(ph);
    float h1 = 0.01f * sinf(ph);
    float lgm2;
    {
        float r2 = fmaf(h0, h0, fmaf(h1, h1, 1e-8f));
        asm("lg2.approx.f32 %0, %1;" : "=f"(lgm2) : "f"(r2));
    }

    const size_t iD = (size_t)b * cL * cD + d;
    const size_t iP = (size_t)b * cL * XPN;

    struct In { float dtv, xv, zv; float2 Bn, Cn; };
    auto LOAD = [&](int t) -> In {
        In r;
        size_t jD = iD + (size_t)t * cD;
        size_t jP = iP + (size_t)t * XPN;
        r.dtv = g_dt[jD];
        r.xv  = g_xdt[jD];
        r.zv  = g_zg[jD];
        r.Bn  = *(const float2*)&g_xp[jP + cR + 2 * n];
        r.Cn  = *(const float2*)&g_xp[jP + cR + 2 * cN + 2 * n];
        return r;
    };

    In pre[2];
    pre[0] = LOAD(0);
    pre[1] = LOAD(1);

    for (int t = 0; t < cL; t++) {
        In cur = pre[t & 1];
        if (t + 2 < cL) pre[t & 1] = LOAD(t + 2);

        // q = 0.25*(1 - alpha): input-only, off the h-chain
        float alpha;
        asm("ex2.approx.f32 %0, %1;" : "=f"(alpha)
            : "f"(cur.dtv * Aneg * 1.4426950408889634f));
        float q = 0.25f * (1.0f - alpha);

        float s1;
        asm("ex2.approx.f32 %0, %1;" : "=f"(s1) : "f"(q * lgm2));

        h0 = fmaf(s1, h0, cur.Bn.x * cur.xv);
        h1 = fmaf(s1, h1, cur.Bn.y * cur.xv);

        float r2b = fmaf(h0, h0, fmaf(h1, h1, 1e-8f));
        float inv = rsqrtf(r2b);
        float m2  = r2b * inv;
        float th;
        asm("tanh.approx.f32 %0, %1;" : "=f"(th) : "f"(m2));
        float sc = th * inv;
        h0 *= sc;
        h1 *= sc;

        // next-step log-magnitude: |h|^2 = tanh(m2)^2 (+eps, matching ref)
        float th2 = fmaf(th, th, 1e-8f);
        asm("lg2.approx.f32 %0, %1;" : "=f"(lgm2) : "f"(th2));

        float yv = fmaf(h0, cur.Cn.x, h1 * cur.Cn.y);
        yv += __shfl_xor_sync(0xffffffffu, yv, 1);
        yv += __shfl_xor_sync(0xffffffffu, yv, 2);
        yv += __shfl_xor_sync(0xffffffffu, yv, 4);
        yv += __shfl_xor_sync(0xffffffffu, yv, 8);
        if (n == 0) g_yg[iD + (size_t)t * cD] = yv * cur.zv;
    }
}

// ---------------------------------------------------------------------------
// kernel_launch
// inputs: x, in_proj_w, x_proj_w, dt_proj_w, dt_proj_b, out_proj_w, out_proj_b, A_log
// ---------------------------------------------------------------------------
extern "C" void kernel_launch(void* const* d_in, const int* in_sizes, int n_in,
                              void* d_out, int out_size) {
    const float* x     = (const float*)d_in[0];
    const float* w_in  = (const float*)d_in[1];
    const float* w_xp  = (const float*)d_in[2];
    const float* w_dt  = (const float*)d_in[3];
    const float* b_dt  = (const float*)d_in[4];
    const float* w_o   = (const float*)d_in[5];
    const float* b_o   = (const float*)d_in[6];
    const float* A_log = (const float*)d_in[7];
    float* out = (float*)d_out;

    float *p_xin, *p_zg, *p_xp, *p_dt, *p_xdt, *p_yg;
    __half *p_winT, *p_wxpT, *p_wdtT, *p_woT;
    cudaGetSymbolAddress((void**)&p_xin,  g_xin);
    cudaGetSymbolAddress((void**)&p_zg,   g_zg);
    cudaGetSymbolAddress((void**)&p_xp,   g_xp);
    cudaGetSymbolAddress((void**)&p_dt,   g_dt);
    cudaGetSymbolAddress((void**)&p_xdt,  g_xdt);
    cudaGetSymbolAddress((void**)&p_yg,   g_yg);
    cudaGetSymbolAddress((void**)&p_winT, g_winT);
    cudaGetSymbolAddress((void**)&p_wxpT, g_wxpT);
    cudaGetSymbolAddress((void**)&p_wdtT, g_wdtT);
    cudaGetSymbolAddress((void**)&p_woT,  g_woT);

    dim3 tb(32, 8);
    // 0) transpose + pad + half-convert all weights to [N][K]
    transpose_pad_h<<<dim3(48, 24), tb>>>(w_in, p_winT, cD, 2 * cD, cD, 2 * cD);
    transpose_pad_h<<<dim3( 4, 24), tb>>>(w_xp, p_wxpT, cD, XPW,   cD, XPN);
    transpose_pad_h<<<dim3(24,  2), tb>>>(w_dt, p_wdtT, cR, cD,    DTK, cD);
    transpose_pad_h<<<dim3(24, 24), tb>>>(w_o,  p_woT,  cD, cD,    cD, cD);

    // 1) in_proj: xin = silu(x@w[:, :D]), zg = silu(x@w[:, D:])
    gemm_h<0><<<dim3(12, 32), 256>>>(
        x, p_winT, p_xin, p_zg, nullptr, nullptr, cD, cD, 0);

    // 2) x_proj: xp = xin @ xpw (M x 128, cols 112..127 = 0 via zero weights)
    gemm_h<1><<<dim3(1, 32), 256>>>(
        p_xin, p_wxpT, p_xp, nullptr, nullptr, nullptr, cD, cD, XPN);

    // 3) dt_proj (K padded to 64; weight cols 48..63 zero):
    //    dt = softplus(xp[:, :48]@w_dt + b); xdt = dt*xin
    gemm_h<2><<<dim3(6, 32), 256>>>(
        p_xp, p_wdtT, p_dt, p_xdt, b_dt, p_xin, DTK, XPN, 0);

    // 4) recurrent scan -> yg = ys * silu(z)
    scan_kernel<<<dim3(cD / 8, cB), 128>>>(A_log);

    // 5) out_proj: out = yg @ w_o + b_o
    gemm_h<3><<<dim3(6, 32), 256>>>(
        p_yg, p_woT, out, nullptr, b_o, nullptr, cD, cD, cD);
}

// round 15
// speedup vs baseline: 1.8681x; 1.0276x over previous
#include <cuda_runtime.h>
#include <cuda_fp16.h>
#include <cstdint>
#include <cstddef>

// ---------------------------------------------------------------------------
// Problem constants
// ---------------------------------------------------------------------------
constexpr int cB = 4;
constexpr int cL = 1024;
constexpr int cD = 768;
constexpr int cN = 16;
constexpr int cR = 48;
constexpr int cM = cB * cL;          // 4096 rows
constexpr int XPW = cR + 4 * cN;     // 112 true x_proj width
constexpr int XPN = 128;             // padded x_proj width
constexpr int DTK = 64;              // padded dt_proj K (48 -> 64)

// ---------------------------------------------------------------------------
// Scratch (static device globals — no allocation)
// ---------------------------------------------------------------------------
__device__ float  g_xin [cM * cD];      // silu(xz[:, :D]) fp32 (scan aux)
__device__ __half g_xinh[cM * cD];      // half copy (x_proj A)
__device__ float  g_zg  [cM * cD];      // silu(xz[:, D:]) fp32 (scan)
__device__ float  g_xp  [cM * XPN];     // x_in @ x_proj_w fp32 (scan B/C)
__device__ __half g_xph [cM * XPN];     // half copy (dt_proj A)
__device__ float  g_dt  [cM * cD];      // softplus(dt_pre) (scan)
__device__ float  g_xdt [cM * cD];      // dt * x_in (scan)
__device__ __half g_ygh [cM * cD];      // half(ys * silu(z)) (out_proj A)
__device__ __half g_xh  [cM * cD];      // half(x) (in_proj A)
__device__ __half g_winT[2 * cD * cD];  // in_proj_w^T   [1536][768]
__device__ __half g_wxpT[XPN * cD];     // x_proj_w^T    [128][768] (rows 112.. = 0)
__device__ __half g_wdtT[cD * DTK];     // dt_proj_w^T   [768][64]  (cols 48.. = 0)
__device__ __half g_woT [cD * cD];      // out_proj_w^T  [768][768]

// ---------------------------------------------------------------------------
// Helpers
// ---------------------------------------------------------------------------
__device__ __forceinline__ uint32_t smem_u32(const void* p) {
    uint32_t a;
    asm("{ .reg .u64 t; cvta.to.shared.u64 t, %1; cvt.u32.u64 %0, t; }"
        : "=r"(a) : "l"(p));
    return a;
}
__device__ __forceinline__ float siluf(float x) { return x / (1.0f + __expf(-x)); }
__device__ __forceinline__ float softplusf(float x) {
    return fmaxf(x, 0.0f) + log1pf(__expf(-fabsf(x)));
}
__device__ __forceinline__ void mma_f16(float* c, const uint32_t* a, const uint32_t* b) {
    asm volatile(
        "mma.sync.aligned.m16n8k16.row.col.f32.f16.f16.f32 "
        "{%0,%1,%2,%3}, {%4,%5,%6,%7}, {%8,%9}, {%0,%1,%2,%3};"
        : "+f"(c[0]), "+f"(c[1]), "+f"(c[2]), "+f"(c[3])
        : "r"(a[0]), "r"(a[1]), "r"(a[2]), "r"(a[3]), "r"(b[0]), "r"(b[1]));
}
__device__ __forceinline__ void ldm_x4(uint32_t* r, uint32_t addr) {
    asm volatile("ldmatrix.sync.aligned.m8n8.x4.shared.b16 {%0,%1,%2,%3}, [%4];"
                 : "=r"(r[0]), "=r"(r[1]), "=r"(r[2]), "=r"(r[3]) : "r"(addr));
}
__device__ __forceinline__ void ldm_x2(uint32_t* r, uint32_t addr) {
    asm volatile("ldmatrix.sync.aligned.m8n8.x2.shared.b16 {%0,%1}, [%2];"
                 : "=r"(r[0]), "=r"(r[1]) : "r"(addr));
}
__device__ __forceinline__ void cp16(uint32_t s, const void* g) {
    asm volatile("cp.async.cg.shared.global [%0], [%1], 16;" :: "r"(s), "l"(g));
}
#define CP_COMMIT() asm volatile("cp.async.commit_group;" ::: "memory")
#define CP_WAIT1()  asm volatile("cp.async.wait_group 1;"  ::: "memory")

// ---------------------------------------------------------------------------
// Epilogues (device globals referenced directly for the half side-copies)
//  0: split-silu + half(xin)   1: plain + half(xp)   2: softplus+x*dt   3: bias
// ---------------------------------------------------------------------------
template<int EPI>
__device__ __forceinline__ void epi_store(int m, int col, float v,
                                          float* C0, float* C1,
                                          const float* bias, const float* aux,
                                          int ldc) {
    if constexpr (EPI == 0) {
        float s = siluf(v);
        if (col < cD) {
            size_t idx = (size_t)m * cD + col;
            C0[idx] = s;
            g_xinh[idx] = __float2half_rn(s);
        } else {
            C1[(size_t)m * cD + (col - cD)] = s;
        }
    } else if constexpr (EPI == 1) {
        size_t idx = (size_t)m * ldc + col;
        C0[idx] = v;
        g_xph[idx] = __float2half_rn(v);
    } else if constexpr (EPI == 2) {
        float dtv = softplusf(v + bias[col]);
        size_t idx = (size_t)m * cD + col;
        C0[idx] = dtv;
        C1[idx] = dtv * aux[idx];
    } else {
        C0[(size_t)m * ldc + col] = v + bias[col];
    }
}

// ---------------------------------------------------------------------------
// fp16 tensor-core GEMM, cp.async 3-stage pipeline.
// C[M,N] = A[M,K] @ Bw^T, A half [M][lda], Bw half [N][K].
// CTA tile 128x128, 256 threads = 8 warps (2m x 4n), warp tile 64x32, BK=32.
// Stage = half[128][40] A + half[128][40] B = 20480 B; 3 stages = 60 KB dyn.
// Row stride 80B: 16B-aligned ldmatrix rows, conflict-free phases
// (banks (20r + c/4) mod 32 distinct over 8 rows).
// ---------------------------------------------------------------------------
constexpr int STG_BYTES = 128 * 40 * 2;        // one operand tile
constexpr int STAGE     = 2 * STG_BYTES;       // A + B
constexpr int GSMEM     = 3 * STAGE;           // 61440

template<int EPI>
__global__ void __launch_bounds__(256, 2) gemm_h(
    const __half* __restrict__ A, const __half* __restrict__ Bw,
    float* __restrict__ C0, float* __restrict__ C1,
    const float* __restrict__ bias, const float* __restrict__ aux,
    int K, int lda, int ldc)
{
    extern __shared__ __align__(16) char smem[];
    const uint32_t sm0 = smem_u32(smem);

    const int tid  = threadIdx.x;
    const int wid  = tid >> 5;
    const int lane = tid & 31;
    const int g    = lane >> 2;
    const int t    = lane & 3;
    const int mw   = (wid & 1) * 64;
    const int nw   = (wid >> 1) * 32;
    const int m0   = blockIdx.y * 128;
    const int n0   = blockIdx.x * 128;

    float c[4][4][4];
#pragma unroll
    for (int im = 0; im < 4; im++)
#pragma unroll
        for (int in_ = 0; in_ < 4; in_++)
#pragma unroll
            for (int r = 0; r < 4; r++) c[im][in_][r] = 0.0f;

    const int aRow = mw + (lane & 15);
    const int aK   = (lane >> 4) * 8;
    const int bRow = nw + (lane & 7);
    const int bK   = ((lane >> 3) & 1) * 8;

    const __half* Ab = A  + (size_t)m0 * lda;
    const __half* Bb = Bw + (size_t)n0 * K;
    const int nk = K / 32;

    // per-thread copy slots: 2 x 16B for A, 2 x 16B for B per stage
    const int cr = tid >> 2, cq = tid & 3;   // row 0..63(+64), col-16B 0..3

    auto ISSUE = [&](int kb, int slot) {
        const __half* Ag = Ab + (size_t)kb * 32;
        const __half* Bg = Bb + (size_t)kb * 32;
        uint32_t sA = sm0 + slot * STAGE;
        uint32_t sB = sA + STG_BYTES;
#pragma unroll
        for (int i = 0; i < 2; i++) {
            int r = cr + i * 64;
            uint32_t off = (uint32_t)(r * 40 + cq * 8) * 2;
            cp16(sA + off, Ag + (size_t)r * lda + cq * 8);
            cp16(sB + off, Bg + (size_t)r * K   + cq * 8);
        }
    };

    // prologue: 2 stages in flight
    ISSUE(0, 0); CP_COMMIT();
    if (nk > 1) ISSUE(1, 1);
    CP_COMMIT();

    for (int kb = 0; kb < nk; kb++) {
        CP_WAIT1();            // stage kb landed
        __syncthreads();       // all warps done with slot (kb-1)%3 too

        if (kb + 2 < nk) ISSUE(kb + 2, (kb + 2) % 3);
        CP_COMMIT();

        const int slot = kb % 3;
        const uint32_t bA = sm0 + slot * STAGE;
        const uint32_t bB = bA + STG_BYTES;
#pragma unroll
        for (int ks = 0; ks < 2; ks++) {
            uint32_t af[4][4];
#pragma unroll
            for (int im = 0; im < 4; im++)
                ldm_x4(af[im], bA + ((aRow + im * 16) * 40 + ks * 16 + aK) * 2);
            uint32_t bf[4][2];
#pragma unroll
            for (int in_ = 0; in_ < 4; in_++)
                ldm_x2(bf[in_], bB + ((bRow + in_ * 8) * 40 + ks * 16 + bK) * 2);
#pragma unroll
            for (int in_ = 0; in_ < 4; in_++)
#pragma unroll
                for (int im = 0; im < 4; im++)
                    mma_f16(c[im][in_], af[im], bf[in_]);
        }
    }

    // Epilogue: c0:(g,2t) c1:(g,2t+1) c2:(g+8,2t) c3:(g+8,2t+1)
#pragma unroll
    for (int im = 0; im < 4; im++) {
        const int row0 = m0 + mw + im * 16 + g;
#pragma unroll
        for (int in_ = 0; in_ < 4; in_++) {
            const int col0 = n0 + nw + in_ * 8 + 2 * t;
            epi_store<EPI>(row0,     col0,     c[im][in_][0], C0, C1, bias, aux, ldc);
            epi_store<EPI>(row0,     col0 + 1, c[im][in_][1], C0, C1, bias, aux, ldc);
            epi_store<EPI>(row0 + 8, col0,     c[im][in_][2], C0, C1, bias, aux, ldc);
            epi_store<EPI>(row0 + 8, col0 + 1, c[im][in_][3], C0, C1, bias, aux, ldc);
        }
    }
}

// ---------------------------------------------------------------------------
// fp32 -> fp16 convert (for x)
// ---------------------------------------------------------------------------
__global__ void f2h_kernel(const float* __restrict__ src, __half* __restrict__ dst,
                           int n4) {
    int i = blockIdx.x * blockDim.x + threadIdx.x;
    if (i >= n4) return;
    float4 v = *(const float4*)(src + i * 4);
    __half2 a = __floats2half2_rn(v.x, v.y);
    __half2 b = __floats2half2_rn(v.z, v.w);
    uint2 u;
    u.x = *reinterpret_cast<uint32_t*>(&a);
    u.y = *reinterpret_cast<uint32_t*>(&b);
    *(uint2*)(dst + i * 4) = u;
}

// ---------------------------------------------------------------------------
// Transpose + pad + convert to half: dst[Np][Kp] = half(src[k][n]), 0-padded.
// ---------------------------------------------------------------------------
__global__ void transpose_pad_h(const float* __restrict__ src, __half* __restrict__ dst,
                                int Ks, int Ns, int Kp, int Np) {
    __shared__ float tsm[32][33];
    int nb = blockIdx.x * 32, kb = blockIdx.y * 32;
#pragma unroll
    for (int i = threadIdx.y; i < 32; i += 8) {
        int k = kb + i, n = nb + threadIdx.x;
        tsm[i][threadIdx.x] = (k < Ks && n < Ns) ? src[(size_t)k * Ns + n] : 0.0f;
    }
    __syncthreads();
#pragma unroll
    for (int i = threadIdx.y; i < 32; i += 8) {
        int n = nb + i, k = kb + threadIdx.x;
        if (n < Np && k < Kp) dst[(size_t)n * Kp + k] = __float2half_rn(tsm[threadIdx.x][i]);
    }
}

// ---------------------------------------------------------------------------
// Sequential scan (log-magnitude carried; writes half yg for out_proj)
// ---------------------------------------------------------------------------
__global__ __launch_bounds__(128)
void scan_kernel(const float* __restrict__ A_log) {
    const int b = blockIdx.y;
    const int n = threadIdx.x & 15;
    const int d = blockIdx.x * 8 + (threadIdx.x >> 4);

    const float Aneg = -__expf(A_log[n]);
    const float ph = (float)n * 0.39269908169872414f;
    float h0 = 0.01f * cosf(ph);
    float h1 = 0.01f * sinf(ph);
    float lgm2;
    {
        float r2 = fmaf(h0, h0, fmaf(h1, h1, 1e-8f));
        asm("lg2.approx.f32 %0, %1;" : "=f"(lgm2) : "f"(r2));
    }

    const size_t iD = (size_t)b * cL * cD + d;
    const size_t iP = (size_t)b * cL * XPN;

    struct In { float dtv, xv, zv; float2 Bn, Cn; };
    auto LOAD = [&](int t) -> In {
        In r;
        size_t jD = iD + (size_t)t * cD;
        size_t jP = iP + (size_t)t * XPN;
        r.dtv = g_dt[jD];
        r.xv  = g_xdt[jD];
        r.zv  = g_zg[jD];
        r.Bn  = *(const float2*)&g_xp[jP + cR + 2 * n];
        r.Cn  = *(const float2*)&g_xp[jP + cR + 2 * cN + 2 * n];
        return r;
    };

    In pre[2];
    pre[0] = LOAD(0);
    pre[1] = LOAD(1);

    for (int t = 0; t < cL; t++) {
        In cur = pre[t & 1];
        if (t + 2 < cL) pre[t & 1] = LOAD(t + 2);

        float alpha;
        asm("ex2.approx.f32 %0, %1;" : "=f"(alpha)
            : "f"(cur.dtv * Aneg * 1.4426950408889634f));
        float q = 0.25f * (1.0f - alpha);

        float s1;
        asm("ex2.approx.f32 %0, %1;" : "=f"(s1) : "f"(q * lgm2));

        h0 = fmaf(s1, h0, cur.Bn.x * cur.xv);
        h1 = fmaf(s1, h1, cur.Bn.y * cur.xv);

        float r2b = fmaf(h0, h0, fmaf(h1, h1, 1e-8f));
        float inv = rsqrtf(r2b);
        float m2  = r2b * inv;
        float th;
        asm("tanh.approx.f32 %0, %1;" : "=f"(th) : "f"(m2));
        float sc = th * inv;
        h0 *= sc;
        h1 *= sc;

        float th2 = fmaf(th, th, 1e-8f);
        asm("lg2.approx.f32 %0, %1;" : "=f"(lgm2) : "f"(th2));

        float yv = fmaf(h0, cur.Cn.x, h1 * cur.Cn.y);
        yv += __shfl_xor_sync(0xffffffffu, yv, 1);
        yv += __shfl_xor_sync(0xffffffffu, yv, 2);
        yv += __shfl_xor_sync(0xffffffffu, yv, 4);
        yv += __shfl_xor_sync(0xffffffffu, yv, 8);
        if (n == 0) g_ygh[iD + (size_t)t * cD] = __float2half_rn(yv * cur.zv);
    }
}

// ---------------------------------------------------------------------------
// kernel_launch
// inputs: x, in_proj_w, x_proj_w, dt_proj_w, dt_proj_b, out_proj_w, out_proj_b, A_log
// ---------------------------------------------------------------------------
extern "C" void kernel_launch(void* const* d_in, const int* in_sizes, int n_in,
                              void* d_out, int out_size) {
    const float* x     = (const float*)d_in[0];
    const float* w_in  = (const float*)d_in[1];
    const float* w_xp  = (const float*)d_in[2];
    const float* w_dt  = (const float*)d_in[3];
    const float* b_dt  = (const float*)d_in[4];
    const float* w_o   = (const float*)d_in[5];
    const float* b_o   = (const float*)d_in[6];
    const float* A_log = (const float*)d_in[7];
    float* out = (float*)d_out;

    float *p_xin, *p_zg, *p_xp, *p_dt, *p_xdt;
    __half *p_xh, *p_xinh, *p_xph, *p_ygh, *p_winT, *p_wxpT, *p_wdtT, *p_woT;
    cudaGetSymbolAddress((void**)&p_xin,  g_xin);
    cudaGetSymbolAddress((void**)&p_zg,   g_zg);
    cudaGetSymbolAddress((void**)&p_xp,   g_xp);
    cudaGetSymbolAddress((void**)&p_dt,   g_dt);
    cudaGetSymbolAddress((void**)&p_xdt,  g_xdt);
    cudaGetSymbolAddress((void**)&p_xh,   g_xh);
    cudaGetSymbolAddress((void**)&p_xinh, g_xinh);
    cudaGetSymbolAddress((void**)&p_xph,  g_xph);
    cudaGetSymbolAddress((void**)&p_ygh,  g_ygh);
    cudaGetSymbolAddress((void**)&p_winT, g_winT);
    cudaGetSymbolAddress((void**)&p_wxpT, g_wxpT);
    cudaGetSymbolAddress((void**)&p_wdtT, g_wdtT);
    cudaGetSymbolAddress((void**)&p_woT,  g_woT);

    static bool attr_done = false;
    if (!attr_done) {
        cudaFuncSetAttribute(gemm_h<0>, cudaFuncAttributeMaxDynamicSharedMemorySize, GSMEM);
        cudaFuncSetAttribute(gemm_h<1>, cudaFuncAttributeMaxDynamicSharedMemorySize, GSMEM);
        cudaFuncSetAttribute(gemm_h<2>, cudaFuncAttributeMaxDynamicSharedMemorySize, GSMEM);
        cudaFuncSetAttribute(gemm_h<3>, cudaFuncAttributeMaxDynamicSharedMemorySize, GSMEM);
        attr_done = true;
    }

    dim3 tb(32, 8);
    // 0) weight prep + x half-convert
    transpose_pad_h<<<dim3(48, 24), tb>>>(w_in, p_winT, cD, 2 * cD, cD, 2 * cD);
    transpose_pad_h<<<dim3( 4, 24), tb>>>(w_xp, p_wxpT, cD, XPW,   cD, XPN);
    transpose_pad_h<<<dim3(24,  2), tb>>>(w_dt, p_wdtT, cR, cD,    DTK, cD);
    transpose_pad_h<<<dim3(24, 24), tb>>>(w_o,  p_woT,  cD, cD,    cD, cD);
    f2h_kernel<<<(cM * cD / 4 + 255) / 256, 256>>>(x, p_xh, cM * cD / 4);

    // 1) in_proj: xin = silu(x@w[:, :D]) (+half), zg = silu(x@w[:, D:])
    gemm_h<0><<<dim3(12, 32), 256, GSMEM>>>(
        p_xh, p_winT, p_xin, p_zg, nullptr, nullptr, cD, cD, 0);

    // 2) x_proj: xp = xin @ xpw (+half)
    gemm_h<1><<<dim3(1, 32), 256, GSMEM>>>(
        p_xinh, p_wxpT, p_xp, nullptr, nullptr, nullptr, cD, cD, XPN);

    // 3) dt_proj (K padded to 64): dt = softplus(xp[:, :48]@w_dt + b); xdt = dt*xin
    gemm_h<2><<<dim3(6, 32), 256, GSMEM>>>(
        p_xph, p_wdtT, p_dt, p_xdt, b_dt, p_xin, DTK, XPN, 0);

    // 4) recurrent scan -> ygh = half(ys * silu(z))
    scan_kernel<<<dim3(cD / 8, cB), 128>>>(A_log);

    // 5) out_proj: out = yg @ w_o + b_o
    gemm_h<3><<<dim3(6, 32), 256, GSMEM>>>(
        p_ygh, p_woT, out, nullptr, b_o, nullptr, cD, cD, cD);
}